// round 10
// baseline (speedup 1.0000x reference)
#include <cuda_runtime.h>

#define BB 16
#define CI 128
#define CO1 128
#define HH 128
#define WW 128
#define COD 256
#define HO 64
#define WO 64

typedef unsigned long long u64;

__device__ __forceinline__ u64 bcast2(float x) {
    u64 r; asm("mov.b64 %0, {%1, %1};" : "=l"(r) : "f"(x)); return r;
}
__device__ __forceinline__ void ffma2(u64& acc, u64 a, u64 b) {
    asm("fma.rn.f32x2 %0, %1, %2, %0;" : "+l"(acc) : "l"(a), "l"(b));
}
__device__ __forceinline__ float2 unpack2(u64 v) {
    float2 f; asm("mov.b64 {%0, %1}, %2;" : "=f"(f.x), "=f"(f.y) : "l"(v)); return f;
}

// scratch (device globals: no allocations allowed)
__device__ float g_x1[BB * CI * HH * WW];
__device__ float g_x2[BB * CI * HH * WW];
__device__ float g_smod1[BB * CI];
__device__ float g_smod2[BB * CI];
__device__ float g_d1[BB * CO1];
__device__ float g_d2[BB * CO1];
__device__ float g_wsq1[CO1 * CI];
__device__ float g_wsq2[CO1 * CI];

// ---------------------------------------------------------------- precompute
__global__ void k_smod(const float* __restrict__ s1, const float* __restrict__ s2) {
    int i = blockIdx.x * 256 + threadIdx.x;
    if (i < BB * CI) {
        g_smod1[i] = s1[i] + 1.f;
        g_smod2[i] = s2[i] + 1.f;
    }
}

__global__ void k_wsq(const float* __restrict__ w1, const float* __restrict__ w2) {
    int i = blockIdx.x * 256 + threadIdx.x;
    if (i < CO1 * CI) {
        float a = 0.f, b = 0.f;
        #pragma unroll
        for (int k = 0; k < 9; k++) {
            float v1 = w1[i * 9 + k];
            float v2 = w2[i * 9 + k];
            a += v1 * v1;
            b += v2 * v2;
        }
        g_wsq1[i] = a;
        g_wsq2[i] = b;
    }
}

__global__ void k_demod() {
    int i = blockIdx.x * 256 + threadIdx.x;  // b*128 + co
    if (i < BB * CO1) {
        int b = i >> 7, co = i & 127;
        float a = 0.f, c = 0.f;
        for (int ci = 0; ci < CI; ci++) {
            float m1 = g_smod1[b * CI + ci];
            float m2 = g_smod2[b * CI + ci];
            float q = g_wsq1[co * CI + ci];
            float r = g_wsq2[co * CI + ci];
            a += m1 * m1 * q;
            c += m2 * m2 * r;
        }
        g_d1[i] = rsqrtf(a + 1e-8f);
        g_d2[i] = rsqrtf(c + 1e-8f);
    }
}

// -------------------------------------------------- modulated 3x3 conv + act
// tile: 64 out-channels x 8h x 16w, 256 threads, each thread 8 co x 4 px
// inner product uses packed fp32x2 FMA over co-pairs
#define TH 8
#define TW 16
#define TO 64
#define CC 8
#define WPAD 68   // weight smem row stride (mult of 4 -> 16B-aligned rows)

__global__ __launch_bounds__(256) void conv3x3_mod(
    const float* __restrict__ x, const float* __restrict__ w,
    const float* __restrict__ smod, const float* __restrict__ dscale,
    const float* __restrict__ res, float* __restrict__ out)
{
    __shared__ __align__(16) float s_in[CC][TH + 2][20];
    __shared__ __align__(16) float s_w[CC * 9][WPAD];

    const int w0  = blockIdx.x * TW;
    const int h0  = blockIdx.y * TH;
    const int b   = blockIdx.z >> 1;
    const int co0 = (blockIdx.z & 1) * TO;

    const int t   = threadIdx.x;
    const int cg  = t >> 5;             // 0..7 -> 8 co each (4 co-pairs)
    const int pg  = t & 31;
    const int hl  = pg >> 2;            // 0..7
    const int wl  = (pg & 3) << 2;      // 0,4,8,12

    u64 acc[4][4];                      // [co-pair][pixel]
    #pragma unroll
    for (int j = 0; j < 4; j++)
        #pragma unroll
        for (int p = 0; p < 4; p++) acc[j][p] = 0ull;

    for (int ci0 = 0; ci0 < CI; ci0 += CC) {
        __syncthreads();
        // input tile, scaled by style modulation
        for (int i = t; i < CC * 10 * 18; i += 256) {
            int ci = i / 180;
            int r  = (i % 180) / 18;
            int c  = i % 18;
            int gh = h0 - 1 + r;
            int gw = w0 - 1 + c;
            float v = 0.f;
            if (gh >= 0 && gh < HH && gw >= 0 && gw < WW)
                v = x[((b * CI + ci0 + ci) * HH + gh) * WW + gw] * smod[b * CI + ci0 + ci];
            s_in[ci][r][c] = v;
        }
        // weights: coalesced gmem read (72 consecutive floats per co)
        for (int i = t; i < CC * 9 * TO; i += 256) {
            int co  = i / (CC * 9);
            int rem = i % (CC * 9);
            s_w[rem][co] = w[(co0 + co) * (CI * 9) + (ci0 + rem / 9) * 9 + (rem % 9)];
        }
        __syncthreads();

        #pragma unroll
        for (int ci = 0; ci < CC; ci++) {
            #pragma unroll
            for (int kh = 0; kh < 3; kh++) {
                const float4* rp = (const float4*)&s_in[ci][hl + kh][0];
                float4 xa = rp[wl >> 2];
                float4 xc = rp[(wl >> 2) + 1];
                u64 xb[6];
                xb[0] = bcast2(xa.x); xb[1] = bcast2(xa.y);
                xb[2] = bcast2(xa.z); xb[3] = bcast2(xa.w);
                xb[4] = bcast2(xc.x); xb[5] = bcast2(xc.y);
                #pragma unroll
                for (int kw = 0; kw < 3; kw++) {
                    const u64* wp = (const u64*)&s_w[ci * 9 + kh * 3 + kw][cg * 8];
                    u64 wpr[4] = {wp[0], wp[1], wp[2], wp[3]};
                    #pragma unroll
                    for (int j = 0; j < 4; j++)
                        #pragma unroll
                        for (int p = 0; p < 4; p++)
                            ffma2(acc[j][p], wpr[j], xb[kw + p]);
                }
            }
        }
    }

    #pragma unroll
    for (int j = 0; j < 4; j++) {
        float a0[4], a1[4];
        #pragma unroll
        for (int p = 0; p < 4; p++) {
            float2 u = unpack2(acc[j][p]);
            a0[p] = u.x; a1[p] = u.y;
        }
        #pragma unroll
        for (int s = 0; s < 2; s++) {
            const float* av = s ? a1 : a0;
            int co = co0 + cg * 8 + 2 * j + s;
            float d = dscale[b * CO1 + co];
            int oi = ((b * CO1 + co) * HH + h0 + hl) * WW + w0 + wl;
            float4 v;
            v.x = av[0] * d; v.y = av[1] * d;
            v.z = av[2] * d; v.w = av[3] * d;
            if (res) {
                float4 r4 = *(const float4*)&res[oi];
                v.x += r4.x; v.y += r4.y; v.z += r4.z; v.w += r4.w;
            }
            v.x = v.x >= 0.f ? v.x : 0.2f * v.x;
            v.y = v.y >= 0.f ? v.y : 0.2f * v.y;
            v.z = v.z >= 0.f ? v.z : 0.2f * v.z;
            v.w = v.w >= 0.f ? v.w : 0.2f * v.w;
            *(float4*)&out[oi] = v;
        }
    }
}

// ----------------------------------------------- 4x4 stride-2 downsample conv
// tile: 64 out-channels x 8oh x 16ow, 256 threads, each thread 8 co x 4 ow
#define DTO 64
#define DCC 4

__global__ __launch_bounds__(256) void conv4x4_down(
    const float* __restrict__ x, const float* __restrict__ w,
    const float* __restrict__ bias, float* __restrict__ out)
{
    __shared__ __align__(16) float s_in[DCC][18][36];
    __shared__ __align__(16) float s_w[DCC * 16][WPAD];

    const int ow0 = blockIdx.x * 16;
    const int oh0 = blockIdx.y * 8;
    const int b   = blockIdx.z >> 2;
    const int co0 = (blockIdx.z & 3) * DTO;

    const int t   = threadIdx.x;
    const int cg  = t >> 5;             // 0..7 -> 8 co each (4 co-pairs)
    const int pg  = t & 31;
    const int ohl = pg >> 2;            // 0..7
    const int owl = (pg & 3) << 2;      // 0,4,8,12

    u64 acc[4][4];
    #pragma unroll
    for (int j = 0; j < 4; j++)
        #pragma unroll
        for (int p = 0; p < 4; p++) acc[j][p] = 0ull;

    const int ih0 = oh0 * 2 - 1;
    const int iw0 = ow0 * 2 - 1;

    for (int ci0 = 0; ci0 < CI; ci0 += DCC) {
        __syncthreads();
        for (int i = t; i < DCC * 18 * 34; i += 256) {
            int ci = i / 612;
            int r  = (i % 612) / 34;
            int c  = i % 34;
            int gh = ih0 + r, gw = iw0 + c;
            float v = 0.f;
            if (gh >= 0 && gh < HH && gw >= 0 && gw < WW)
                v = x[((b * CI + ci0 + ci) * HH + gh) * WW + gw];
            s_in[ci][r][c] = v;
        }
        for (int i = t; i < DCC * 16 * DTO; i += 256) {
            int co  = i / (DCC * 16);
            int rem = i % (DCC * 16);
            s_w[rem][co] = w[(co0 + co) * (CI * 16) + (ci0 + rem / 16) * 16 + (rem % 16)];
        }
        __syncthreads();

        #pragma unroll
        for (int ci = 0; ci < DCC; ci++) {
            #pragma unroll
            for (int kh = 0; kh < 4; kh++) {
                const float4* rp = (const float4*)&s_in[ci][ohl * 2 + kh][0];
                int base = owl >> 1;
                float4 x0 = rp[base], x1 = rp[base + 1], x2 = rp[base + 2];
                float xw[10] = {x0.x, x0.y, x0.z, x0.w,
                                x1.x, x1.y, x1.z, x1.w,
                                x2.x, x2.y};
                u64 xb[10];
                #pragma unroll
                for (int q = 0; q < 10; q++) xb[q] = bcast2(xw[q]);
                #pragma unroll
                for (int kw = 0; kw < 4; kw++) {
                    const u64* wp = (const u64*)&s_w[ci * 16 + kh * 4 + kw][cg * 8];
                    u64 wpr[4] = {wp[0], wp[1], wp[2], wp[3]};
                    #pragma unroll
                    for (int j = 0; j < 4; j++)
                        #pragma unroll
                        for (int p = 0; p < 4; p++)
                            ffma2(acc[j][p], wpr[j], xb[kw + 2 * p]);
                }
            }
        }
    }

    #pragma unroll
    for (int j = 0; j < 4; j++) {
        float a0[4], a1[4];
        #pragma unroll
        for (int p = 0; p < 4; p++) {
            float2 u = unpack2(acc[j][p]);
            a0[p] = u.x; a1[p] = u.y;
        }
        #pragma unroll
        for (int s = 0; s < 2; s++) {
            const float* av = s ? a1 : a0;
            int co = co0 + cg * 8 + 2 * j + s;
            float bv = bias[co];
            int oi = ((b * COD + co) * HO + oh0 + ohl) * WO + ow0 + owl;
            float4 v;
            v.x = av[0] + bv; v.y = av[1] + bv;
            v.z = av[2] + bv; v.w = av[3] + bv;
            *(float4*)&out[oi] = v;
        }
    }
}

// --------------------------------------------------------------------- launch
extern "C" void kernel_launch(void* const* d_in, const int* in_sizes, int n_in,
                              void* d_out, int out_size) {
    const float* features = (const float*)d_in[0];
    const float* smean1   = (const float*)d_in[1];
    const float* sstd1    = (const float*)d_in[2];   // used as s2 per reference
    const float* w1       = (const float*)d_in[6];
    const float* w2       = (const float*)d_in[7];
    const float* down_w   = (const float*)d_in[8];
    const float* down_b   = (const float*)d_in[9];
    float* out = (float*)d_out;

    float *x1, *x2, *smod1, *smod2, *d1, *d2;
    cudaGetSymbolAddress((void**)&x1, g_x1);
    cudaGetSymbolAddress((void**)&x2, g_x2);
    cudaGetSymbolAddress((void**)&smod1, g_smod1);
    cudaGetSymbolAddress((void**)&smod2, g_smod2);
    cudaGetSymbolAddress((void**)&d1, g_d1);
    cudaGetSymbolAddress((void**)&d2, g_d2);

    k_smod<<<(BB * CI + 255) / 256, 256>>>(smean1, sstd1);
    k_wsq<<<(CO1 * CI + 255) / 256, 256>>>(w1, w2);
    k_demod<<<(BB * CO1 + 255) / 256, 256>>>();

    dim3 g1(WW / TW, HH / TH, BB * (CO1 / TO));   // (8,16,32)
    conv3x3_mod<<<g1, 256>>>(features, w1, smod1, d1, nullptr, x1);
    conv3x3_mod<<<g1, 256>>>(x1, w2, smod2, d2, x1, x2);

    dim3 g2(WO / 16, HO / 8, BB * (COD / DTO));   // (4,8,64)
    conv4x4_down<<<g2, 256>>>(x2, down_w, down_b, out);
}

// round 11
// speedup vs baseline: 1.0007x; 1.0007x over previous
#include <cuda_runtime.h>

#define BB 16
#define CI 128
#define CO1 128
#define HH 128
#define WW 128
#define COD 256
#define HO 64
#define WO 64

typedef unsigned long long u64;

__device__ __forceinline__ u64 bcast2(float x) {
    u64 r; asm("mov.b64 %0, {%1, %1};" : "=l"(r) : "f"(x)); return r;
}
__device__ __forceinline__ void ffma2(u64& acc, u64 a, u64 b) {
    asm("fma.rn.f32x2 %0, %1, %2, %0;" : "+l"(acc) : "l"(a), "l"(b));
}
__device__ __forceinline__ float2 unpack2(u64 v) {
    float2 f; asm("mov.b64 {%0, %1}, %2;" : "=f"(f.x), "=f"(f.y) : "l"(v)); return f;
}

// scratch (device globals: no allocations allowed)
__device__ float g_x1[BB * CI * HH * WW];
__device__ float g_x2[BB * CI * HH * WW];
__device__ float g_smod1[BB * CI];
__device__ float g_smod2[BB * CI];
__device__ float g_d1[BB * CO1];
__device__ float g_d2[BB * CO1];
__device__ float g_wsq1[CO1 * CI];
__device__ float g_wsq2[CO1 * CI];

// ---------------------------------------------------------------- precompute
__global__ void k_smod(const float* __restrict__ s1, const float* __restrict__ s2) {
    int i = blockIdx.x * 256 + threadIdx.x;
    if (i < BB * CI) {
        g_smod1[i] = s1[i] + 1.f;
        g_smod2[i] = s2[i] + 1.f;
    }
}

__global__ void k_wsq(const float* __restrict__ w1, const float* __restrict__ w2) {
    int i = blockIdx.x * 256 + threadIdx.x;
    if (i < CO1 * CI) {
        float a = 0.f, b = 0.f;
        #pragma unroll
        for (int k = 0; k < 9; k++) {
            float v1 = w1[i * 9 + k];
            float v2 = w2[i * 9 + k];
            a += v1 * v1;
            b += v2 * v2;
        }
        g_wsq1[i] = a;
        g_wsq2[i] = b;
    }
}

__global__ void k_demod() {
    int i = blockIdx.x * 256 + threadIdx.x;  // b*128 + co
    if (i < BB * CO1) {
        int b = i >> 7, co = i & 127;
        float a = 0.f, c = 0.f;
        for (int ci = 0; ci < CI; ci++) {
            float m1 = g_smod1[b * CI + ci];
            float m2 = g_smod2[b * CI + ci];
            float q = g_wsq1[co * CI + ci];
            float r = g_wsq2[co * CI + ci];
            a += m1 * m1 * q;
            c += m2 * m2 * r;
        }
        g_d1[i] = rsqrtf(a + 1e-8f);
        g_d2[i] = rsqrtf(c + 1e-8f);
    }
}

// -------------------------------------------------- modulated 3x3 conv + act
// tile: 64 out-channels x 8h x 16w, 256 threads, each thread 8 co x 4 px
// inner product uses packed fp32x2 FMA over co-pairs
#define TH 8
#define TW 16
#define TO 64
#define CC 8
#define WPAD 68   // weight smem row stride (mult of 4 -> 16B-aligned rows)

__global__ __launch_bounds__(256) void conv3x3_mod(
    const float* __restrict__ x, const float* __restrict__ w,
    const float* __restrict__ smod, const float* __restrict__ dscale,
    const float* __restrict__ res, float* __restrict__ out)
{
    __shared__ __align__(16) float s_in[CC][TH + 2][20];
    __shared__ __align__(16) float s_w[CC * 9][WPAD];

    const int w0  = blockIdx.x * TW;
    const int h0  = blockIdx.y * TH;
    const int b   = blockIdx.z >> 1;
    const int co0 = (blockIdx.z & 1) * TO;

    const int t   = threadIdx.x;
    const int cg  = t >> 5;             // 0..7 -> 8 co each (4 co-pairs)
    const int pg  = t & 31;
    const int hl  = pg >> 2;            // 0..7
    const int wl  = (pg & 3) << 2;      // 0,4,8,12

    u64 acc[4][4];                      // [co-pair][pixel]
    #pragma unroll
    for (int j = 0; j < 4; j++)
        #pragma unroll
        for (int p = 0; p < 4; p++) acc[j][p] = 0ull;

    for (int ci0 = 0; ci0 < CI; ci0 += CC) {
        __syncthreads();
        // input tile, scaled by style modulation
        for (int i = t; i < CC * 10 * 18; i += 256) {
            int ci = i / 180;
            int r  = (i % 180) / 18;
            int c  = i % 18;
            int gh = h0 - 1 + r;
            int gw = w0 - 1 + c;
            float v = 0.f;
            if (gh >= 0 && gh < HH && gw >= 0 && gw < WW)
                v = x[((b * CI + ci0 + ci) * HH + gh) * WW + gw] * smod[b * CI + ci0 + ci];
            s_in[ci][r][c] = v;
        }
        // weights: coalesced gmem read (72 consecutive floats per co)
        for (int i = t; i < CC * 9 * TO; i += 256) {
            int co  = i / (CC * 9);
            int rem = i % (CC * 9);
            s_w[rem][co] = w[(co0 + co) * (CI * 9) + (ci0 + rem / 9) * 9 + (rem % 9)];
        }
        __syncthreads();

        #pragma unroll
        for (int ci = 0; ci < CC; ci++) {
            #pragma unroll
            for (int kh = 0; kh < 3; kh++) {
                const float4* rp = (const float4*)&s_in[ci][hl + kh][0];
                float4 xa = rp[wl >> 2];
                float4 xc = rp[(wl >> 2) + 1];
                u64 xb[6];
                xb[0] = bcast2(xa.x); xb[1] = bcast2(xa.y);
                xb[2] = bcast2(xa.z); xb[3] = bcast2(xa.w);
                xb[4] = bcast2(xc.x); xb[5] = bcast2(xc.y);
                #pragma unroll
                for (int kw = 0; kw < 3; kw++) {
                    const u64* wp = (const u64*)&s_w[ci * 9 + kh * 3 + kw][cg * 8];
                    u64 wpr[4] = {wp[0], wp[1], wp[2], wp[3]};
                    #pragma unroll
                    for (int j = 0; j < 4; j++)
                        #pragma unroll
                        for (int p = 0; p < 4; p++)
                            ffma2(acc[j][p], wpr[j], xb[kw + p]);
                }
            }
        }
    }

    #pragma unroll
    for (int j = 0; j < 4; j++) {
        float a0[4], a1[4];
        #pragma unroll
        for (int p = 0; p < 4; p++) {
            float2 u = unpack2(acc[j][p]);
            a0[p] = u.x; a1[p] = u.y;
        }
        #pragma unroll
        for (int s = 0; s < 2; s++) {
            const float* av = s ? a1 : a0;
            int co = co0 + cg * 8 + 2 * j + s;
            float d = dscale[b * CO1 + co];
            int oi = ((b * CO1 + co) * HH + h0 + hl) * WW + w0 + wl;
            float4 v;
            v.x = av[0] * d; v.y = av[1] * d;
            v.z = av[2] * d; v.w = av[3] * d;
            if (res) {
                float4 r4 = *(const float4*)&res[oi];
                v.x += r4.x; v.y += r4.y; v.z += r4.z; v.w += r4.w;
            }
            v.x = v.x >= 0.f ? v.x : 0.2f * v.x;
            v.y = v.y >= 0.f ? v.y : 0.2f * v.y;
            v.z = v.z >= 0.f ? v.z : 0.2f * v.z;
            v.w = v.w >= 0.f ? v.w : 0.2f * v.w;
            *(float4*)&out[oi] = v;
        }
    }
}

// ----------------------------------------------- 4x4 stride-2 downsample conv
// tile: 64 out-channels x 8oh x 16ow, 256 threads, each thread 8 co x 4 ow
#define DTO 64
#define DCC 4

__global__ __launch_bounds__(256) void conv4x4_down(
    const float* __restrict__ x, const float* __restrict__ w,
    const float* __restrict__ bias, float* __restrict__ out)
{
    __shared__ __align__(16) float s_in[DCC][18][36];
    __shared__ __align__(16) float s_w[DCC * 16][WPAD];

    const int ow0 = blockIdx.x * 16;
    const int oh0 = blockIdx.y * 8;
    const int b   = blockIdx.z >> 2;
    const int co0 = (blockIdx.z & 3) * DTO;

    const int t   = threadIdx.x;
    const int cg  = t >> 5;             // 0..7 -> 8 co each (4 co-pairs)
    const int pg  = t & 31;
    const int ohl = pg >> 2;            // 0..7
    const int owl = (pg & 3) << 2;      // 0,4,8,12

    u64 acc[4][4];
    #pragma unroll
    for (int j = 0; j < 4; j++)
        #pragma unroll
        for (int p = 0; p < 4; p++) acc[j][p] = 0ull;

    const int ih0 = oh0 * 2 - 1;
    const int iw0 = ow0 * 2 - 1;

    for (int ci0 = 0; ci0 < CI; ci0 += DCC) {
        __syncthreads();
        for (int i = t; i < DCC * 18 * 34; i += 256) {
            int ci = i / 612;
            int r  = (i % 612) / 34;
            int c  = i % 34;
            int gh = ih0 + r, gw = iw0 + c;
            float v = 0.f;
            if (gh >= 0 && gh < HH && gw >= 0 && gw < WW)
                v = x[((b * CI + ci0 + ci) * HH + gh) * WW + gw];
            s_in[ci][r][c] = v;
        }
        for (int i = t; i < DCC * 16 * DTO; i += 256) {
            int co  = i / (DCC * 16);
            int rem = i % (DCC * 16);
            s_w[rem][co] = w[(co0 + co) * (CI * 16) + (ci0 + rem / 16) * 16 + (rem % 16)];
        }
        __syncthreads();

        #pragma unroll
        for (int ci = 0; ci < DCC; ci++) {
            #pragma unroll
            for (int kh = 0; kh < 4; kh++) {
                const float4* rp = (const float4*)&s_in[ci][ohl * 2 + kh][0];
                int base = owl >> 1;
                float4 x0 = rp[base], x1 = rp[base + 1], x2 = rp[base + 2];
                float xw[10] = {x0.x, x0.y, x0.z, x0.w,
                                x1.x, x1.y, x1.z, x1.w,
                                x2.x, x2.y};
                u64 xb[10];
                #pragma unroll
                for (int q = 0; q < 10; q++) xb[q] = bcast2(xw[q]);
                #pragma unroll
                for (int kw = 0; kw < 4; kw++) {
                    const u64* wp = (const u64*)&s_w[ci * 16 + kh * 4 + kw][cg * 8];
                    u64 wpr[4] = {wp[0], wp[1], wp[2], wp[3]};
                    #pragma unroll
                    for (int j = 0; j < 4; j++)
                        #pragma unroll
                        for (int p = 0; p < 4; p++)
                            ffma2(acc[j][p], wpr[j], xb[kw + 2 * p]);
                }
            }
        }
    }

    #pragma unroll
    for (int j = 0; j < 4; j++) {
        float a0[4], a1[4];
        #pragma unroll
        for (int p = 0; p < 4; p++) {
            float2 u = unpack2(acc[j][p]);
            a0[p] = u.x; a1[p] = u.y;
        }
        #pragma unroll
        for (int s = 0; s < 2; s++) {
            const float* av = s ? a1 : a0;
            int co = co0 + cg * 8 + 2 * j + s;
            float bv = bias[co];
            int oi = ((b * COD + co) * HO + oh0 + ohl) * WO + ow0 + owl;
            float4 v;
            v.x = av[0] + bv; v.y = av[1] + bv;
            v.z = av[2] + bv; v.w = av[3] + bv;
            *(float4*)&out[oi] = v;
        }
    }
}

// --------------------------------------------------------------------- launch
extern "C" void kernel_launch(void* const* d_in, const int* in_sizes, int n_in,
                              void* d_out, int out_size) {
    const float* features = (const float*)d_in[0];
    const float* smean1   = (const float*)d_in[1];
    const float* sstd1    = (const float*)d_in[2];   // used as s2 per reference
    const float* w1       = (const float*)d_in[6];
    const float* w2       = (const float*)d_in[7];
    const float* down_w   = (const float*)d_in[8];
    const float* down_b   = (const float*)d_in[9];
    float* out = (float*)d_out;

    float *x1, *x2, *smod1, *smod2, *d1, *d2;
    cudaGetSymbolAddress((void**)&x1, g_x1);
    cudaGetSymbolAddress((void**)&x2, g_x2);
    cudaGetSymbolAddress((void**)&smod1, g_smod1);
    cudaGetSymbolAddress((void**)&smod2, g_smod2);
    cudaGetSymbolAddress((void**)&d1, g_d1);
    cudaGetSymbolAddress((void**)&d2, g_d2);

    k_smod<<<(BB * CI + 255) / 256, 256>>>(smean1, sstd1);
    k_wsq<<<(CO1 * CI + 255) / 256, 256>>>(w1, w2);
    k_demod<<<(BB * CO1 + 255) / 256, 256>>>();

    dim3 g1(WW / TW, HH / TH, BB * (CO1 / TO));   // (8,16,32)
    conv3x3_mod<<<g1, 256>>>(features, w1, smod1, d1, nullptr, x1);
    conv3x3_mod<<<g1, 256>>>(x1, w2, smod2, d2, x1, x2);

    dim3 g2(WO / 16, HO / 8, BB * (COD / DTO));   // (4,8,64)
    conv4x4_down<<<g2, 256>>>(x2, down_w, down_b, out);
}